// round 12
// baseline (speedup 1.0000x reference)
#include <cuda_runtime.h>
#include <cuda_fp16.h>

#define Bk      4
#define Ck      256
#define Pk      2304      // 48*48
#define INTERk  128
#define HEADSk  8
#define HDk     16

typedef unsigned long long u64;
typedef unsigned int u32;

// ---- helpers --------------------------------------------------------------
__device__ __forceinline__ u32 h2(float lo, float hi) {
    u32 r; asm("cvt.rn.f16x2.f32 %0,%1,%2;" : "=r"(r) : "f"(hi), "f"(lo)); return r;
}
__device__ __forceinline__ u32 ex2h2(u32 x) {
    u32 r; asm("ex2.approx.f16x2 %0,%1;" : "=r"(r) : "r"(x)); return r;
}
__device__ __forceinline__ u32 hadd2(u32 a, u32 b) {
    u32 r; asm("add.rn.f16x2 %0,%1,%2;" : "=r"(r) : "r"(a), "r"(b)); return r;
}
__device__ __forceinline__ float2 h2f(u32 h) {
    float2 f;
    asm("{.reg .f16 l,h; mov.b32 {l,h},%2; cvt.f32.f16 %0,l; cvt.f32.f16 %1,h;}"
        : "=f"(f.x), "=f"(f.y) : "r"(h));
    return f;
}
// mma m16n8k16 fp16 -> f32 accum (accumulating)
__device__ __forceinline__ void mma16816(float c[4], const u32 a[4], const u32 b[2]) {
    asm("mma.sync.aligned.m16n8k16.row.col.f32.f16.f16.f32 "
        "{%0,%1,%2,%3},{%4,%5,%6,%7},{%8,%9},{%0,%1,%2,%3};"
        : "+f"(c[0]), "+f"(c[1]), "+f"(c[2]), "+f"(c[3])
        : "r"(a[0]), "r"(a[1]), "r"(a[2]), "r"(a[3]), "r"(b[0]), "r"(b[1]));
}
// mma with C = 0 (no accumulator zero-init MOVs; RZ-backed)
__device__ __forceinline__ void mma16816z(float d[4], const u32 a[4], const u32 b[2]) {
    asm("mma.sync.aligned.m16n8k16.row.col.f32.f16.f16.f32 "
        "{%0,%1,%2,%3},{%4,%5,%6,%7},{%8,%9},{%10,%11,%12,%13};"
        : "=f"(d[0]), "=f"(d[1]), "=f"(d[2]), "=f"(d[3])
        : "r"(a[0]), "r"(a[1]), "r"(a[2]), "r"(a[3]), "r"(b[0]), "r"(b[1]),
          "f"(0.f), "f"(0.f), "f"(0.f), "f"(0.f));
}
__device__ __forceinline__ u32 smaddr(const void* p) {
    return (u32)__cvta_generic_to_shared(p);
}
__device__ __forceinline__ void ldmT4(u32 a[4], u32 addr) {
    asm volatile("ldmatrix.sync.aligned.m8n8.x4.trans.shared.b16 {%0,%1,%2,%3},[%4];"
        : "=r"(a[0]), "=r"(a[1]), "=r"(a[2]), "=r"(a[3]) : "r"(addr) : "memory");
}
__device__ __forceinline__ void ldmT2(u32 b[2], u32 addr) {
    asm volatile("ldmatrix.sync.aligned.m8n8.x2.trans.shared.b16 {%0,%1},[%2];"
        : "=r"(b[0]), "=r"(b[1]) : "r"(addr) : "memory");
}
__device__ __forceinline__ void ldm4(u32 a[4], u32 addr) {
    asm volatile("ldmatrix.sync.aligned.m8n8.x4.shared.b16 {%0,%1,%2,%3},[%4];"
        : "=r"(a[0]), "=r"(a[1]), "=r"(a[2]), "=r"(a[3]) : "r"(addr) : "memory");
}
__device__ __forceinline__ void ldA(u32 a[4], const __half* base, int stride,
                                    int mbase, int kbase, int lane) {
    const __half* p = base + (size_t)(mbase + (lane >> 2)) * stride + kbase + (lane & 3) * 2;
    a[0] = *(const u32*)p;
    a[1] = *(const u32*)(p + 8 * stride);
    a[2] = *(const u32*)(p + 8);
    a[3] = *(const u32*)(p + 8 * stride + 8);
}
__device__ __forceinline__ void ldB(u32 b[2], const __half* base, int stride,
                                    int nbase, int kbase, int lane) {
    const __half* p = base + (size_t)(nbase + (lane >> 2)) * stride + kbase + (lane & 3) * 2;
    b[0] = *(const u32*)p;
    b[1] = *(const u32*)(p + 8);
}

// Scratch (device globals), all fp16
__device__ __half gQ[(size_t)Bk * HEADSk * Pk * HDk];   // [b][h][p][d], pre-scaled
__device__ __half gK[(size_t)Bk * HEADSk * Pk * HDk];   // [b][h][p][d]
__device__ __half gVt[(size_t)Bk * HEADSk * HDk * Pk];  // [b][h][d][p]
__device__ __half gO[(size_t)Bk * Pk * INTERk];         // [b][p][ci]

// ---------------------------------------------------------------------------
// Kernel 1: QKV projection, fp16 HMMA.
// grid = (Pk/128, B, 6): z6>>1 = input (rgb/depth/rgbd), z6&1 = co half.
// Tile: 128px x 64co. W (64co x 256k) staged whole once; X double-buffered.
// 3 CTAs/SM. Dynamic smem 51200 B.
// ---------------------------------------------------------------------------
#define PWS 264   // W row stride (k 256 + pad 8): 528B rows, conflict-free frags
#define PXS 136   // X row stride: 272B rows, conflict-free ldmatrix
#define PROJ_SMEM ((64 * PWS + 2 * 32 * PXS) * 2)

__global__ __launch_bounds__(256, 3) void proj_kernel(
    const float* __restrict__ rgb, const float* __restrict__ depth, const float* __restrict__ rgbd,
    const float* __restrict__ Wq, const float* __restrict__ bq,
    const float* __restrict__ Wk, const float* __restrict__ bk,
    const float* __restrict__ Wv, const float* __restrict__ bv)
{
    extern __shared__ __half psm[];
    __half* Ws = psm;                 // [64][PWS]
    __half* Xs = psm + 64 * PWS;      // [2][32][PXS]

    const int z6  = blockIdx.z;
    const int z   = z6 >> 1;          // input / weight select
    const int cob = z6 & 1;           // co half (0..1) of 128
    const float* x    = (z == 0) ? rgb : (z == 1) ? depth : rgbd;
    const float* W    = (z == 0) ? Wq  : (z == 1) ? Wk    : Wv;
    const float* bias = (z == 0) ? bq  : (z == 1) ? bk    : bv;

    const int b    = blockIdx.y;
    const int px0  = blockIdx.x * 128;
    const int t    = threadIdx.x;
    const int lane = t & 31;
    const int w    = t >> 5;

    // z<2 mapping: wm = px 32-block (4), wn = co 32-block (2)
    // z==2 mapping: wm2 = co 32-block (2), wn2 = px 32-block (4)
    const int wm  = w >> 1, wn  = w & 1;
    const int wm2 = w & 1,  wn2 = w >> 1;

    float c[8][4];
    #pragma unroll
    for (int i = 0; i < 8; i++)
        #pragma unroll
        for (int j = 0; j < 4; j++) c[i][j] = 0.f;

    // ---- stage whole W tile: 64co x 256k ----
    {
        const int co = t >> 2, ks = (t & 3) * 64;
        const float* wr = W + (size_t)(cob * 64 + co) * Ck + ks;
        #pragma unroll
        for (int j = 0; j < 4; j++) {
            const float4 f0 = *(const float4*)(wr + j * 16);
            const float4 f1 = *(const float4*)(wr + j * 16 + 4);
            const float4 f2 = *(const float4*)(wr + j * 16 + 8);
            const float4 f3 = *(const float4*)(wr + j * 16 + 12);
            uint4 p, q;
            p.x = h2(f0.x, f0.y); p.y = h2(f0.z, f0.w);
            p.z = h2(f1.x, f1.y); p.w = h2(f1.z, f1.w);
            q.x = h2(f2.x, f2.y); q.y = h2(f2.z, f2.w);
            q.z = h2(f3.x, f3.y); q.w = h2(f3.z, f3.w);
            *(uint4*)&Ws[co * PWS + ks + j * 16]     = p;
            *(uint4*)&Ws[co * PWS + ks + j * 16 + 8] = q;
        }
    }

    const float* xb = x + (size_t)b * Ck * Pk + px0;
    const int xk = t >> 4, xp8 = (t & 15) * 8;
    float4 pxa0, pxa1, pxb0, pxb1;

    auto ldg_x = [&](int kc) {
        const int ci0 = kc * 32;
        const float* xr = xb + (size_t)(ci0 + xk) * Pk + xp8;
        pxa0 = *(const float4*)(xr);
        pxa1 = *(const float4*)(xr + 4);
        const float* xr2 = xb + (size_t)(ci0 + xk + 16) * Pk + xp8;
        pxb0 = *(const float4*)(xr2);
        pxb1 = *(const float4*)(xr2 + 4);
    };
    auto sts_x = [&](int buf) {
        uint4 xa, xbv;
        xa.x = h2(pxa0.x, pxa0.y);  xa.y = h2(pxa0.z, pxa0.w);
        xa.z = h2(pxa1.x, pxa1.y);  xa.w = h2(pxa1.z, pxa1.w);
        xbv.x = h2(pxb0.x, pxb0.y); xbv.y = h2(pxb0.z, pxb0.w);
        xbv.z = h2(pxb1.x, pxb1.y); xbv.w = h2(pxb1.z, pxb1.w);
        __half* xd = Xs + buf * 32 * PXS;
        *(uint4*)&xd[xk * PXS + xp8]        = xa;
        *(uint4*)&xd[(xk + 16) * PXS + xp8] = xbv;
    };

    ldg_x(0);
    sts_x(0);

    for (int kc = 0; kc < 8; kc++) {
        __syncthreads();
        if (kc < 7) ldg_x(kc + 1);
        const __half* XsB = Xs + (kc & 1) * 32 * PXS;

        if (z < 2) {
            // C[px][co]: A = X (ldmatrix.trans), B = W
            #pragma unroll
            for (int k16 = 0; k16 < 2; k16++) {
                const int row  = k16 * 16 + ((lane & 16) >> 1) + (lane & 7);
                #pragma unroll
                for (int mt = 0; mt < 2; mt++) {
                    u32 a[4];
                    ldmT4(a, smaddr(XsB + row * PXS + wm * 32 + mt * 16 + (lane & 8)));
                    #pragma unroll
                    for (int nt = 0; nt < 4; nt++) {
                        u32 bb[2];
                        ldB(bb, Ws, PWS, wn * 32 + nt * 8, kc * 32 + k16 * 16, lane);
                        mma16816(c[mt * 4 + nt], a, bb);
                    }
                }
            }
        } else {
            // C[co][px]: A = W, B = X (ldmatrix.trans)
            #pragma unroll
            for (int k16 = 0; k16 < 2; k16++) {
                const int rowB = k16 * 16 + (lane & 15);
                #pragma unroll
                for (int mt = 0; mt < 2; mt++) {
                    u32 a[4];
                    ldA(a, Ws, PWS, wm2 * 32 + mt * 16, kc * 32 + k16 * 16, lane);
                    #pragma unroll
                    for (int nt = 0; nt < 4; nt++) {
                        u32 bb[2];
                        ldmT2(bb, smaddr(XsB + rowB * PXS + wn2 * 32 + nt * 8));
                        mma16816(c[mt * 4 + nt], a, bb);
                    }
                }
            }
        }
        if (kc < 7) sts_x((kc + 1) & 1);
    }

    // epilogue
    if (z < 2) {
        const float sc = (z == 0) ? 0.360673760f : 1.0f;   // Q: 0.25*log2(e)
        __half* dst = (z == 0) ? gQ : gK;
        #pragma unroll
        for (int mt = 0; mt < 2; mt++)
            #pragma unroll
            for (int nt = 0; nt < 4; nt++) {
                const float* cc = c[mt * 4 + nt];
                const int px = px0 + wm * 32 + mt * 16 + (lane >> 2);
                const int co = cob * 64 + wn * 32 + nt * 8 + (lane & 3) * 2;
                const int head = co >> 4, d = co & 15;
                const size_t base = (size_t)(b * HEADSk + head) * Pk;
                const float b0 = bias[co], b1 = bias[co + 1];
                *(u32*)&dst[(base + px) * HDk + d]     = h2((cc[0] + b0) * sc, (cc[1] + b1) * sc);
                *(u32*)&dst[(base + px + 8) * HDk + d] = h2((cc[2] + b0) * sc, (cc[3] + b1) * sc);
            }
    } else {
        #pragma unroll
        for (int mt = 0; mt < 2; mt++)
            #pragma unroll
            for (int nt = 0; nt < 4; nt++) {
                const float* cc = c[mt * 4 + nt];
                const int px = px0 + wn2 * 32 + nt * 8 + (lane & 3) * 2;
                #pragma unroll
                for (int half = 0; half < 2; half++) {
                    const int co = cob * 64 + wm2 * 32 + mt * 16 + (lane >> 2) + half * 8;
                    const int head = co >> 4, d = co & 15;
                    const float bb = bias[co];
                    *(u32*)&gVt[((size_t)(b * HEADSk + head) * HDk + d) * Pk + px] =
                        h2(cc[half * 2] + bb, cc[half * 2 + 1] + bb);
                }
            }
    }
}

// ---------------------------------------------------------------------------
// Kernel 2: attention, fp16 HMMA, ldmatrix frags, zero-C MMA, f16x2 exp.
// grid = (P/128, HEADS, B), block = 256; warp owns 16 q rows.
// ---------------------------------------------------------------------------
__global__ __launch_bounds__(256, 2) void attn_kernel()
{
    __shared__ __half Ks[2][128][24];
    __shared__ __half Vs[2][16][136];

    const int tid  = threadIdx.x;
    const int lane = tid & 31;
    const int w    = tid >> 5;
    const int b = blockIdx.z, h = blockIdx.y;
    const size_t bh = (size_t)(b * HEADSk + h);
    const int qw = blockIdx.x * 128 + w * 16;

    const __half* Qb = gQ  + bh * Pk * HDk;
    const __half* Kb = gK  + bh * Pk * HDk;
    const __half* Vb = gVt + bh * HDk * Pk;

    u32 aQ[4];
    {
        const __half* qp = Qb + (size_t)(qw + (lane >> 2)) * HDk + (lane & 3) * 2;
        aQ[0] = *(const u32*)(qp);
        aQ[1] = *(const u32*)(qp + 8 * HDk);
        aQ[2] = *(const u32*)(qp + 8);
        aQ[3] = *(const u32*)(qp + 8 * HDk + 8);
    }

    float O0[4] = {0.f, 0.f, 0.f, 0.f};
    float O1[4] = {0.f, 0.f, 0.f, 0.f};
    float l0 = 0.f, l1 = 0.f;

    uint4 pk0, pk1, pv;
    const int vd = tid >> 4, vseg = (tid & 15) * 8;

    auto ldg_tile = [&](int kt) {
        if (tid < 128) {
            const uint4* src = (const uint4*)(Kb + (size_t)(kt + tid) * HDk);
            pk0 = src[0];
            pk1 = src[1];
        }
        pv = *(const uint4*)(Vb + (size_t)vd * Pk + kt + vseg);
    };
    auto sts_tile = [&](int buf) {
        if (tid < 128) {
            *(uint4*)&Ks[buf][tid][0] = pk0;
            *(uint4*)&Ks[buf][tid][8] = pk1;
        }
        *(uint4*)&Vs[buf][vd][vseg] = pv;
    };

    ldg_tile(0);
    sts_tile(0);

    // ldmatrix lane-address components (fixed per thread)
    const int krow_lo = ((lane >> 4) * 8) + (lane & 7);   // within nt-pair
    const int kcol    = ((lane >> 3) & 1) * 8;
    const int vrow    = (lane & 7) + ((lane >> 4) * 8);   // d row
    // vcol = kk*16 + kcol

    #pragma unroll 2
    for (int it = 0; it < Pk / 128; it++) {
        __syncthreads();
        if (it < Pk / 128 - 1) ldg_tile((it + 1) * 128);
        const int buf = it & 1;

        // S = Q K^T: 8 ldmatrix.x4 + 16 zero-C MMAs
        float S[16][4];
        #pragma unroll
        for (int ntp = 0; ntp < 8; ntp++) {
            u32 bK[4];
            ldm4(bK, smaddr(&Ks[buf][ntp * 16 + krow_lo][kcol]));
            mma16816z(S[ntp * 2],     aQ, bK);
            mma16816z(S[ntp * 2 + 1], aQ, bK + 2);
        }

        // packed fp16 exp
        u32 e[16][2];
        #pragma unroll
        for (int nt = 0; nt < 16; nt++) {
            e[nt][0] = ex2h2(h2(S[nt][0], S[nt][1]));
            e[nt][1] = ex2h2(h2(S[nt][2], S[nt][3]));
        }
        // tile row-sums in f16x2, flush to f32 once per tile
        u32 ta = e[0][0], tb = e[0][1];
        #pragma unroll
        for (int nt = 1; nt < 16; nt++) {
            ta = hadd2(ta, e[nt][0]);
            tb = hadd2(tb, e[nt][1]);
        }
        const float2 fa = h2f(ta), fb = h2f(tb);
        l0 += fa.x + fa.y;
        l1 += fb.x + fb.y;

        // O += P V: 8 ldmatrix.x4 + 16 MMAs
        #pragma unroll
        for (int kk = 0; kk < 8; kk++) {
            u32 aP[4];
            aP[0] = e[2 * kk][0];
            aP[1] = e[2 * kk][1];
            aP[2] = e[2 * kk + 1][0];
            aP[3] = e[2 * kk + 1][1];
            u32 bV[4];
            ldm4(bV, smaddr(&Vs[buf][vrow][kk * 16 + kcol]));
            mma16816(O0, aP, bV);
            mma16816(O1, aP, bV + 2);
        }
        if (it < Pk / 128 - 1) sts_tile((it + 1) & 1);
    }

    l0 += __shfl_xor_sync(0xffffffffu, l0, 1);
    l0 += __shfl_xor_sync(0xffffffffu, l0, 2);
    l1 += __shfl_xor_sync(0xffffffffu, l1, 1);
    l1 += __shfl_xor_sync(0xffffffffu, l1, 2);
    const float i0 = 1.f / l0;
    const float i1 = 1.f / l1;

    const int q = qw + (lane >> 2);
    __half* Ob = gO + ((size_t)b * Pk) * INTERk + h * HDk;
    #pragma unroll
    for (int nd = 0; nd < 2; nd++) {
        const float* o = nd ? O1 : O0;
        const int d = nd * 8 + (lane & 3) * 2;
        *(u32*)&Ob[(size_t)q * INTERk + d]       = h2(o[0] * i0, o[1] * i0);
        *(u32*)&Ob[(size_t)(q + 8) * INTERk + d] = h2(o[2] * i1, o[3] * i1);
    }
}

// ---------------------------------------------------------------------------
// Kernel 3: output projection, single-stage, fp16 HMMA + bias + 3x residual.
// Residual inputs prefetched to L2 before the MMA phase.
// ---------------------------------------------------------------------------
#define OUT_SMEM ((128 + 64) * 136 * 2)

__global__ __launch_bounds__(256) void out_kernel(
    const float* __restrict__ rgb, const float* __restrict__ depth, const float* __restrict__ rgbd,
    const float* __restrict__ Wo, const float* __restrict__ bo,
    float* __restrict__ out)
{
    extern __shared__ __half dsm[];
    __half* Wos = dsm;              // [128][136]
    __half* Os  = dsm + 128 * 136;  // [64][136]

    const int b    = blockIdx.z;
    const int cob  = blockIdx.y;
    const int px0  = blockIdx.x * 64;
    const int t    = threadIdx.x;
    const int lane = t & 31;
    const int w    = t >> 5;
    const int wm   = w >> 1;
    const int wn   = w & 1;

    {
        const int co = t >> 1, ci0 = (t & 1) * 64;
        const float* wr = Wo + (size_t)(cob * 128 + co) * INTERk + ci0;
        #pragma unroll
        for (int i = 0; i < 4; i++) {
            const float4 f0 = *(const float4*)(wr + i * 16);
            const float4 f1 = *(const float4*)(wr + i * 16 + 4);
            const float4 f2 = *(const float4*)(wr + i * 16 + 8);
            const float4 f3 = *(const float4*)(wr + i * 16 + 12);
            uint4 p, q;
            p.x = h2(f0.x, f0.y); p.y = h2(f0.z, f0.w);
            p.z = h2(f1.x, f1.y); p.w = h2(f1.z, f1.w);
            q.x = h2(f2.x, f2.y); q.y = h2(f2.z, f2.w);
            q.z = h2(f3.x, f3.y); q.w = h2(f3.z, f3.w);
            *(uint4*)&Wos[co * 136 + ci0 + i * 16]     = p;
            *(uint4*)&Wos[co * 136 + ci0 + i * 16 + 8] = q;
        }
    }
    {
        const int px = t >> 2, ci0 = (t & 3) * 32;
        const __half* src = gO + ((size_t)b * Pk + px0 + px) * INTERk + ci0;
        *(uint4*)&Os[px * 136 + ci0]      = *(const uint4*)(src);
        *(uint4*)&Os[px * 136 + ci0 + 8]  = *(const uint4*)(src + 8);
        *(uint4*)&Os[px * 136 + ci0 + 16] = *(const uint4*)(src + 16);
        *(uint4*)&Os[px * 136 + ci0 + 24] = *(const uint4*)(src + 24);
    }
    // L2 prefetch of residual inputs (consumed in the epilogue)
    {
        const int co = t >> 1, half = t & 1;
        const size_t idx = ((size_t)b * Ck + cob * 128 + co) * Pk + px0 + half * 32;
        asm volatile("prefetch.global.L2 [%0];" :: "l"(rgb + idx));
        asm volatile("prefetch.global.L2 [%0];" :: "l"(depth + idx));
        asm volatile("prefetch.global.L2 [%0];" :: "l"(rgbd + idx));
    }
    __syncthreads();

    float c[8][4];
    #pragma unroll
    for (int i = 0; i < 8; i++)
        #pragma unroll
        for (int j = 0; j < 4; j++) c[i][j] = 0.f;

    #pragma unroll
    for (int k16 = 0; k16 < 8; k16++) {
        u32 a0[4], a1[4];
        ldA(a0, Wos, 136, wm * 32,      k16 * 16, lane);
        ldA(a1, Wos, 136, wm * 32 + 16, k16 * 16, lane);
        #pragma unroll
        for (int nt = 0; nt < 4; nt++) {
            u32 bb[2];
            ldB(bb, Os, 136, wn * 32 + nt * 8, k16 * 16, lane);
            mma16816(c[nt],     a0, bb);
            mma16816(c[4 + nt], a1, bb);
        }
    }

    const size_t N1 = (size_t)Bk * Ck * Pk;
    #pragma unroll
    for (int mt = 0; mt < 2; mt++)
        #pragma unroll
        for (int nt = 0; nt < 4; nt++) {
            const float* cc = c[mt * 4 + nt];
            const int px = px0 + wn * 32 + nt * 8 + (lane & 3) * 2;
            #pragma unroll
            for (int half = 0; half < 2; half++) {
                const int co = cob * 128 + wm * 32 + mt * 16 + (lane >> 2) + half * 8;
                const float bb = bo[co];
                const float r0 = cc[half * 2]     + bb;
                const float r1 = cc[half * 2 + 1] + bb;
                const size_t idx = ((size_t)b * Ck + co) * Pk + px;
                const float2 a0 = *(const float2*)(rgb   + idx);
                const float2 a1 = *(const float2*)(depth + idx);
                const float2 a2 = *(const float2*)(rgbd  + idx);
                *(float2*)(out + idx)          = make_float2(a0.x + r0, a0.y + r1);
                *(float2*)(out + N1 + idx)     = make_float2(a1.x + r0, a1.y + r1);
                *(float2*)(out + 2 * N1 + idx) = make_float2(a2.x + r0, a2.y + r1);
            }
        }
}

// ---------------------------------------------------------------------------
extern "C" void kernel_launch(void* const* d_in, const int* in_sizes, int n_in,
                              void* d_out, int out_size)
{
    const float* rgb   = (const float*)d_in[0];
    const float* depth = (const float*)d_in[1];
    const float* rgbd  = (const float*)d_in[2];
    const float* Wq = (const float*)d_in[3];
    const float* bq = (const float*)d_in[4];
    const float* Wk = (const float*)d_in[5];
    const float* bk = (const float*)d_in[6];
    const float* Wv = (const float*)d_in[7];
    const float* bv = (const float*)d_in[8];
    const float* Wo = (const float*)d_in[9];
    const float* bo = (const float*)d_in[10];
    float* out = (float*)d_out;

    static bool attr_set = false;
    if (!attr_set) {
        cudaFuncSetAttribute(proj_kernel, cudaFuncAttributeMaxDynamicSharedMemorySize, PROJ_SMEM);
        cudaFuncSetAttribute(out_kernel, cudaFuncAttributeMaxDynamicSharedMemorySize, OUT_SMEM);
        attr_set = true;
    }

    proj_kernel<<<dim3(Pk / 128, Bk, 6), 256, PROJ_SMEM>>>(rgb, depth, rgbd,
                                                           Wq, bq, Wk, bk, Wv, bv);
    attn_kernel<<<dim3(Pk / 128, HEADSk, Bk), 256>>>();
    out_kernel<<<dim3(Pk / 64, 2, Bk), 256, OUT_SMEM>>>(rgb, depth, rgbd, Wo, bo, out);
}

// round 14
// speedup vs baseline: 1.0468x; 1.0468x over previous
#include <cuda_runtime.h>
#include <cuda_fp16.h>

#define Bk      4
#define Ck      256
#define Pk      2304      // 48*48
#define INTERk  128
#define HEADSk  8
#define HDk     16

typedef unsigned long long u64;
typedef unsigned int u32;

// ---- helpers --------------------------------------------------------------
__device__ __forceinline__ u32 h2(float lo, float hi) {
    u32 r; asm("cvt.rn.f16x2.f32 %0,%1,%2;" : "=r"(r) : "f"(hi), "f"(lo)); return r;
}
__device__ __forceinline__ u32 ex2h2(u32 x) {
    u32 r; asm("ex2.approx.f16x2 %0,%1;" : "=r"(r) : "r"(x)); return r;
}
__device__ __forceinline__ u32 hadd2(u32 a, u32 b) {
    u32 r; asm("add.rn.f16x2 %0,%1,%2;" : "=r"(r) : "r"(a), "r"(b)); return r;
}
__device__ __forceinline__ float2 h2f(u32 h) {
    float2 f;
    asm("{.reg .f16 l,h; mov.b32 {l,h},%2; cvt.f32.f16 %0,l; cvt.f32.f16 %1,h;}"
        : "=f"(f.x), "=f"(f.y) : "r"(h));
    return f;
}
// mma m16n8k16 fp16 -> f32 accum (accumulating)
__device__ __forceinline__ void mma16816(float c[4], const u32 a[4], const u32 b[2]) {
    asm("mma.sync.aligned.m16n8k16.row.col.f32.f16.f16.f32 "
        "{%0,%1,%2,%3},{%4,%5,%6,%7},{%8,%9},{%0,%1,%2,%3};"
        : "+f"(c[0]), "+f"(c[1]), "+f"(c[2]), "+f"(c[3])
        : "r"(a[0]), "r"(a[1]), "r"(a[2]), "r"(a[3]), "r"(b[0]), "r"(b[1]));
}
// mma m16n8k16 fp16 -> f16 accum, C = 0 (for scores: d pairs feed ex2.f16x2 directly)
__device__ __forceinline__ void mma16816hz(u32 d[2], const u32 a[4], const u32 b[2]) {
    asm("mma.sync.aligned.m16n8k16.row.col.f16.f16.f16.f16 "
        "{%0,%1},{%2,%3,%4,%5},{%6,%7},{%8,%9};"
        : "=r"(d[0]), "=r"(d[1])
        : "r"(a[0]), "r"(a[1]), "r"(a[2]), "r"(a[3]), "r"(b[0]), "r"(b[1]),
          "r"(0u), "r"(0u));
}
__device__ __forceinline__ u32 smaddr(const void* p) {
    return (u32)__cvta_generic_to_shared(p);
}
__device__ __forceinline__ void ldmT4(u32 a[4], u32 addr) {
    asm volatile("ldmatrix.sync.aligned.m8n8.x4.trans.shared.b16 {%0,%1,%2,%3},[%4];"
        : "=r"(a[0]), "=r"(a[1]), "=r"(a[2]), "=r"(a[3]) : "r"(addr) : "memory");
}
__device__ __forceinline__ void ldmT2(u32 b[2], u32 addr) {
    asm volatile("ldmatrix.sync.aligned.m8n8.x2.trans.shared.b16 {%0,%1},[%2];"
        : "=r"(b[0]), "=r"(b[1]) : "r"(addr) : "memory");
}
__device__ __forceinline__ void ldm4(u32 a[4], u32 addr) {
    asm volatile("ldmatrix.sync.aligned.m8n8.x4.shared.b16 {%0,%1,%2,%3},[%4];"
        : "=r"(a[0]), "=r"(a[1]), "=r"(a[2]), "=r"(a[3]) : "r"(addr) : "memory");
}
__device__ __forceinline__ void ldA(u32 a[4], const __half* base, int stride,
                                    int mbase, int kbase, int lane) {
    const __half* p = base + (size_t)(mbase + (lane >> 2)) * stride + kbase + (lane & 3) * 2;
    a[0] = *(const u32*)p;
    a[1] = *(const u32*)(p + 8 * stride);
    a[2] = *(const u32*)(p + 8);
    a[3] = *(const u32*)(p + 8 * stride + 8);
}
__device__ __forceinline__ void ldB(u32 b[2], const __half* base, int stride,
                                    int nbase, int kbase, int lane) {
    const __half* p = base + (size_t)(nbase + (lane >> 2)) * stride + kbase + (lane & 3) * 2;
    b[0] = *(const u32*)p;
    b[1] = *(const u32*)(p + 8);
}

// Scratch (device globals), all fp16
__device__ __half gQ[(size_t)Bk * HEADSk * Pk * HDk];   // [b][h][p][d], pre-scaled
__device__ __half gK[(size_t)Bk * HEADSk * Pk * HDk];   // [b][h][p][d]
__device__ __half gVt[(size_t)Bk * HEADSk * HDk * Pk];  // [b][h][d][p]
__device__ __half gO[(size_t)Bk * Pk * INTERk];         // [b][p][ci]

#define WS_STRIDE 40
#define XS2       136

// ---------------------------------------------------------------------------
// Kernel 1: QKV projection, fp16 HMMA, double-buffered + reg prefetch.
// (R9 version — 128px x 128co tile, X staged once per block.)
// ---------------------------------------------------------------------------
__global__ __launch_bounds__(256, 2) void proj_kernel(
    const float* __restrict__ rgb, const float* __restrict__ depth, const float* __restrict__ rgbd,
    const float* __restrict__ Wq, const float* __restrict__ bq,
    const float* __restrict__ Wk, const float* __restrict__ bk,
    const float* __restrict__ Wv, const float* __restrict__ bv)
{
    __shared__ __half Ws[2][128 * WS_STRIDE];
    __shared__ __half Xs[2][32 * XS2];

    const int z = blockIdx.z;
    const float* x    = (z == 0) ? rgb : (z == 1) ? depth : rgbd;
    const float* W    = (z == 0) ? Wq  : (z == 1) ? Wk    : Wv;
    const float* bias = (z == 0) ? bq  : (z == 1) ? bk    : bv;

    const int b    = blockIdx.y;
    const int px0  = blockIdx.x * 128;
    const int t    = threadIdx.x;
    const int lane = t & 31;
    const int w    = t >> 5;
    const int wm   = w >> 1;
    const int wn   = w & 1;

    float c[16][4];
    #pragma unroll
    for (int i = 0; i < 16; i++)
        #pragma unroll
        for (int j = 0; j < 4; j++) c[i][j] = 0.f;

    const float* xb = x + (size_t)b * Ck * Pk + px0;

    float4 pw0, pw1, pw2, pw3;
    float4 pxa0, pxa1, pxb0, pxb1;

    const int wco = t >> 1, wkh = (t & 1) * 16;
    const int xk  = t >> 4, xp8 = (t & 15) * 8;

    auto ldg_chunk = [&](int kc) {
        const int ci0 = kc * 32;
        const float* wr = W + (size_t)wco * Ck + ci0 + wkh;
        pw0 = *(const float4*)(wr + 0);
        pw1 = *(const float4*)(wr + 4);
        pw2 = *(const float4*)(wr + 8);
        pw3 = *(const float4*)(wr + 12);
        const float* xr = xb + (size_t)(ci0 + xk) * Pk + xp8;
        pxa0 = *(const float4*)(xr);
        pxa1 = *(const float4*)(xr + 4);
        const float* xr2 = xb + (size_t)(ci0 + xk + 16) * Pk + xp8;
        pxb0 = *(const float4*)(xr2);
        pxb1 = *(const float4*)(xr2 + 4);
    };
    auto sts_chunk = [&](int buf) {
        uint4 p0, p1;
        p0.x = h2(pw0.x, pw0.y); p0.y = h2(pw0.z, pw0.w);
        p0.z = h2(pw1.x, pw1.y); p0.w = h2(pw1.z, pw1.w);
        p1.x = h2(pw2.x, pw2.y); p1.y = h2(pw2.z, pw2.w);
        p1.z = h2(pw3.x, pw3.y); p1.w = h2(pw3.z, pw3.w);
        *(uint4*)&Ws[buf][wco * WS_STRIDE + wkh]     = p0;
        *(uint4*)&Ws[buf][wco * WS_STRIDE + wkh + 8] = p1;
        uint4 xa, xbv;
        xa.x = h2(pxa0.x, pxa0.y);  xa.y = h2(pxa0.z, pxa0.w);
        xa.z = h2(pxa1.x, pxa1.y);  xa.w = h2(pxa1.z, pxa1.w);
        xbv.x = h2(pxb0.x, pxb0.y); xbv.y = h2(pxb0.z, pxb0.w);
        xbv.z = h2(pxb1.x, pxb1.y); xbv.w = h2(pxb1.z, pxb1.w);
        *(uint4*)&Xs[buf][xk * XS2 + xp8]        = xa;
        *(uint4*)&Xs[buf][(xk + 16) * XS2 + xp8] = xbv;
    };

    ldg_chunk(0);
    sts_chunk(0);

    #pragma unroll 2
    for (int kc = 0; kc < 8; kc++) {
        __syncthreads();
        if (kc < 7) ldg_chunk(kc + 1);

        const int buf = kc & 1;
        const __half* XsB = &Xs[buf][0];
        const __half* WsB = &Ws[buf][0];

        if (z < 2) {
            #pragma unroll
            for (int k16 = 0; k16 < 2; k16++) {
                u32 a0[4], a1[4];
                const int row  = k16 * 16 + ((lane & 16) >> 1) + (lane & 7);
                const int col0 = wm * 32 + (lane & 8);
                ldmT4(a0, smaddr(XsB + row * XS2 + col0));
                ldmT4(a1, smaddr(XsB + row * XS2 + col0 + 16));
                #pragma unroll
                for (int nt = 0; nt < 8; nt++) {
                    u32 bb[2];
                    ldB(bb, WsB, WS_STRIDE, wn * 64 + nt * 8, k16 * 16, lane);
                    mma16816(c[nt],     a0, bb);
                    mma16816(c[8 + nt], a1, bb);
                }
            }
        } else {
            #pragma unroll
            for (int k16 = 0; k16 < 2; k16++) {
                u32 a0[4], a1[4];
                ldA(a0, WsB, WS_STRIDE, wm * 32,      k16 * 16, lane);
                ldA(a1, WsB, WS_STRIDE, wm * 32 + 16, k16 * 16, lane);
                const int rowB = k16 * 16 + (lane & 15);
                #pragma unroll
                for (int nt = 0; nt < 8; nt++) {
                    u32 bb[2];
                    ldmT2(bb, smaddr(XsB + rowB * XS2 + wn * 64 + nt * 8));
                    mma16816(c[nt],     a0, bb);
                    mma16816(c[8 + nt], a1, bb);
                }
            }
        }
        if (kc < 7) sts_chunk((kc + 1) & 1);
    }

    // epilogue
    if (z < 2) {
        const float sc = (z == 0) ? 0.360673760f : 1.0f;   // Q: 0.25*log2(e)
        __half* dst = (z == 0) ? gQ : gK;
        #pragma unroll
        for (int mt = 0; mt < 2; mt++)
            #pragma unroll
            for (int nt = 0; nt < 8; nt++) {
                const float* cc = c[mt * 8 + nt];
                const int px = px0 + wm * 32 + mt * 16 + (lane >> 2);
                const int co = wn * 64 + nt * 8 + (lane & 3) * 2;
                const int head = co >> 4, d = co & 15;
                const size_t base = (size_t)(b * HEADSk + head) * Pk;
                const float b0 = bias[co], b1 = bias[co + 1];
                *(u32*)&dst[(base + px) * HDk + d]     = h2((cc[0] + b0) * sc, (cc[1] + b1) * sc);
                *(u32*)&dst[(base + px + 8) * HDk + d] = h2((cc[2] + b0) * sc, (cc[3] + b1) * sc);
            }
    } else {
        #pragma unroll
        for (int mt = 0; mt < 2; mt++)
            #pragma unroll
            for (int nt = 0; nt < 8; nt++) {
                const float* cc = c[mt * 8 + nt];
                const int px = px0 + wn * 64 + nt * 8 + (lane & 3) * 2;
                #pragma unroll
                for (int half = 0; half < 2; half++) {
                    const int co = wm * 32 + mt * 16 + (lane >> 2) + half * 8;
                    const int head = co >> 4, d = co & 15;
                    const float bb = bias[co];
                    *(u32*)&gVt[((size_t)(b * HEADSk + head) * HDk + d) * Pk + px] =
                        h2(cc[half * 2] + bb, cc[half * 2 + 1] + bb);
                }
            }
    }
}

// ---------------------------------------------------------------------------
// Kernel 2: attention. S via fp16-accum HMMA (d pairs -> ex2.f16x2 directly),
// PV via f32-accum HMMA. ldmatrix frags, double-buffered K/V.
// grid = (P/128, HEADS, B), block = 256; warp owns 16 q rows.
// ---------------------------------------------------------------------------
__global__ __launch_bounds__(256, 2) void attn_kernel()
{
    __shared__ __half Ks[2][128][24];
    __shared__ __half Vs[2][16][136];

    const int tid  = threadIdx.x;
    const int lane = tid & 31;
    const int w    = tid >> 5;
    const int b = blockIdx.z, h = blockIdx.y;
    const size_t bh = (size_t)(b * HEADSk + h);
    const int qw = blockIdx.x * 128 + w * 16;

    const __half* Qb = gQ  + bh * Pk * HDk;
    const __half* Kb = gK  + bh * Pk * HDk;
    const __half* Vb = gVt + bh * HDk * Pk;

    u32 aQ[4];
    {
        const __half* qp = Qb + (size_t)(qw + (lane >> 2)) * HDk + (lane & 3) * 2;
        aQ[0] = *(const u32*)(qp);
        aQ[1] = *(const u32*)(qp + 8 * HDk);
        aQ[2] = *(const u32*)(qp + 8);
        aQ[3] = *(const u32*)(qp + 8 * HDk + 8);
    }

    float O0[4] = {0.f, 0.f, 0.f, 0.f};
    float O1[4] = {0.f, 0.f, 0.f, 0.f};
    float l0 = 0.f, l1 = 0.f;

    uint4 pk0, pk1, pv;
    const int vd = tid >> 4, vseg = (tid & 15) * 8;

    auto ldg_tile = [&](int kt) {
        if (tid < 128) {
            const uint4* src = (const uint4*)(Kb + (size_t)(kt + tid) * HDk);
            pk0 = src[0];
            pk1 = src[1];
        }
        pv = *(const uint4*)(Vb + (size_t)vd * Pk + kt + vseg);
    };
    auto sts_tile = [&](int buf) {
        if (tid < 128) {
            *(uint4*)&Ks[buf][tid][0] = pk0;
            *(uint4*)&Ks[buf][tid][8] = pk1;
        }
        *(uint4*)&Vs[buf][vd][vseg] = pv;
    };

    ldg_tile(0);
    sts_tile(0);

    // ldmatrix lane-address components (fixed per thread)
    const int krow_lo = ((lane >> 4) * 8) + (lane & 7);
    const int kcol    = ((lane >> 3) & 1) * 8;
    const int vrow    = (lane & 7) + ((lane >> 4) * 8);

    #pragma unroll 2
    for (int it = 0; it < Pk / 128; it++) {
        __syncthreads();
        if (it < Pk / 128 - 1) ldg_tile((it + 1) * 128);
        const int buf = it & 1;

        // S = Q K^T (f16 accum) -> e = ex2(S) packed
        u32 e[16][2];
        #pragma unroll
        for (int ntp = 0; ntp < 8; ntp++) {
            u32 bK[4];
            ldm4(bK, smaddr(&Ks[buf][ntp * 16 + krow_lo][kcol]));
            u32 d0[2], d1[2];
            mma16816hz(d0, aQ, bK);
            mma16816hz(d1, aQ, bK + 2);
            e[ntp * 2][0]     = ex2h2(d0[0]);
            e[ntp * 2][1]     = ex2h2(d0[1]);
            e[ntp * 2 + 1][0] = ex2h2(d1[0]);
            e[ntp * 2 + 1][1] = ex2h2(d1[1]);
        }

        // tile row-sums in f16x2, flush to f32 once per tile
        u32 ta = e[0][0], tb = e[0][1];
        #pragma unroll
        for (int nt = 1; nt < 16; nt++) {
            ta = hadd2(ta, e[nt][0]);
            tb = hadd2(tb, e[nt][1]);
        }
        const float2 fa = h2f(ta), fb = h2f(tb);
        l0 += fa.x + fa.y;
        l1 += fb.x + fb.y;

        // O += P V
        #pragma unroll
        for (int kk = 0; kk < 8; kk++) {
            u32 aP[4];
            aP[0] = e[2 * kk][0];
            aP[1] = e[2 * kk][1];
            aP[2] = e[2 * kk + 1][0];
            aP[3] = e[2 * kk + 1][1];
            u32 bV[4];
            ldm4(bV, smaddr(&Vs[buf][vrow][kk * 16 + kcol]));
            mma16816(O0, aP, bV);
            mma16816(O1, aP, bV + 2);
        }
        if (it < Pk / 128 - 1) sts_tile((it + 1) & 1);
    }

    l0 += __shfl_xor_sync(0xffffffffu, l0, 1);
    l0 += __shfl_xor_sync(0xffffffffu, l0, 2);
    l1 += __shfl_xor_sync(0xffffffffu, l1, 1);
    l1 += __shfl_xor_sync(0xffffffffu, l1, 2);
    const float i0 = 1.f / l0;
    const float i1 = 1.f / l1;

    const int q = qw + (lane >> 2);
    __half* Ob = gO + ((size_t)b * Pk) * INTERk + h * HDk;
    #pragma unroll
    for (int nd = 0; nd < 2; nd++) {
        const float* o = nd ? O1 : O0;
        const int d = nd * 8 + (lane & 3) * 2;
        *(u32*)&Ob[(size_t)q * INTERk + d]       = h2(o[0] * i0, o[1] * i0);
        *(u32*)&Ob[(size_t)(q + 8) * INTERk + d] = h2(o[2] * i1, o[3] * i1);
    }
}

// ---------------------------------------------------------------------------
// Kernel 3: output projection, single-stage, fp16 HMMA + bias + 3x residual.
// ---------------------------------------------------------------------------
#define OUT_SMEM ((128 + 64) * 136 * 2)

__global__ __launch_bounds__(256) void out_kernel(
    const float* __restrict__ rgb, const float* __restrict__ depth, const float* __restrict__ rgbd,
    const float* __restrict__ Wo, const float* __restrict__ bo,
    float* __restrict__ out)
{
    extern __shared__ __half dsm[];
    __half* Wos = dsm;              // [128][136]
    __half* Os  = dsm + 128 * 136;  // [64][136]

    const int b    = blockIdx.z;
    const int cob  = blockIdx.y;
    const int px0  = blockIdx.x * 64;
    const int t    = threadIdx.x;
    const int lane = t & 31;
    const int w    = t >> 5;
    const int wm   = w >> 1;
    const int wn   = w & 1;

    {
        const int co = t >> 1, ci0 = (t & 1) * 64;
        const float* wr = Wo + (size_t)(cob * 128 + co) * INTERk + ci0;
        #pragma unroll
        for (int i = 0; i < 4; i++) {
            const float4 f0 = *(const float4*)(wr + i * 16);
            const float4 f1 = *(const float4*)(wr + i * 16 + 4);
            const float4 f2 = *(const float4*)(wr + i * 16 + 8);
            const float4 f3 = *(const float4*)(wr + i * 16 + 12);
            uint4 p, q;
            p.x = h2(f0.x, f0.y); p.y = h2(f0.z, f0.w);
            p.z = h2(f1.x, f1.y); p.w = h2(f1.z, f1.w);
            q.x = h2(f2.x, f2.y); q.y = h2(f2.z, f2.w);
            q.z = h2(f3.x, f3.y); q.w = h2(f3.z, f3.w);
            *(uint4*)&Wos[co * 136 + ci0 + i * 16]     = p;
            *(uint4*)&Wos[co * 136 + ci0 + i * 16 + 8] = q;
        }
    }
    {
        const int px = t >> 2, ci0 = (t & 3) * 32;
        const __half* src = gO + ((size_t)b * Pk + px0 + px) * INTERk + ci0;
        *(uint4*)&Os[px * 136 + ci0]      = *(const uint4*)(src);
        *(uint4*)&Os[px * 136 + ci0 + 8]  = *(const uint4*)(src + 8);
        *(uint4*)&Os[px * 136 + ci0 + 16] = *(const uint4*)(src + 16);
        *(uint4*)&Os[px * 136 + ci0 + 24] = *(const uint4*)(src + 24);
    }
    // L2 prefetch of residual inputs (consumed in the epilogue)
    {
        const int co = t >> 1, half = t & 1;
        const size_t idx = ((size_t)b * Ck + cob * 128 + co) * Pk + px0 + half * 32;
        asm volatile("prefetch.global.L2 [%0];" :: "l"(rgb + idx));
        asm volatile("prefetch.global.L2 [%0];" :: "l"(depth + idx));
        asm volatile("prefetch.global.L2 [%0];" :: "l"(rgbd + idx));
    }
    __syncthreads();

    float c[8][4];
    #pragma unroll
    for (int i = 0; i < 8; i++)
        #pragma unroll
        for (int j = 0; j < 4; j++) c[i][j] = 0.f;

    #pragma unroll
    for (int k16 = 0; k16 < 8; k16++) {
        u32 a0[4], a1[4];
        ldA(a0, Wos, 136, wm * 32,      k16 * 16, lane);
        ldA(a1, Wos, 136, wm * 32 + 16, k16 * 16, lane);
        #pragma unroll
        for (int nt = 0; nt < 4; nt++) {
            u32 bb[2];
            ldB(bb, Os, 136, wn * 32 + nt * 8, k16 * 16, lane);
            mma16816(c[nt],     a0, bb);
            mma16816(c[4 + nt], a1, bb);
        }
    }

    const size_t N1 = (size_t)Bk * Ck * Pk;
    #pragma unroll
    for (int mt = 0; mt < 2; mt++)
        #pragma unroll
        for (int nt = 0; nt < 4; nt++) {
            const float* cc = c[mt * 4 + nt];
            const int px = px0 + wn * 32 + nt * 8 + (lane & 3) * 2;
            #pragma unroll
            for (int half = 0; half < 2; half++) {
                const int co = cob * 128 + wm * 32 + mt * 16 + (lane >> 2) + half * 8;
                const float bb = bo[co];
                const float r0 = cc[half * 2]     + bb;
                const float r1 = cc[half * 2 + 1] + bb;
                const size_t idx = ((size_t)b * Ck + co) * Pk + px;
                const float2 a0 = *(const float2*)(rgb   + idx);
                const float2 a1 = *(const float2*)(depth + idx);
                const float2 a2 = *(const float2*)(rgbd  + idx);
                *(float2*)(out + idx)          = make_float2(a0.x + r0, a0.y + r1);
                *(float2*)(out + N1 + idx)     = make_float2(a1.x + r0, a1.y + r1);
                *(float2*)(out + 2 * N1 + idx) = make_float2(a2.x + r0, a2.y + r1);
            }
        }
}

// ---------------------------------------------------------------------------
extern "C" void kernel_launch(void* const* d_in, const int* in_sizes, int n_in,
                              void* d_out, int out_size)
{
    const float* rgb   = (const float*)d_in[0];
    const float* depth = (const float*)d_in[1];
    const float* rgbd  = (const float*)d_in[2];
    const float* Wq = (const float*)d_in[3];
    const float* bq = (const float*)d_in[4];
    const float* Wk = (const float*)d_in[5];
    const float* bk = (const float*)d_in[6];
    const float* Wv = (const float*)d_in[7];
    const float* bv = (const float*)d_in[8];
    const float* Wo = (const float*)d_in[9];
    const float* bo = (const float*)d_in[10];
    float* out = (float*)d_out;

    static bool attr_set = false;
    if (!attr_set) {
        cudaFuncSetAttribute(out_kernel, cudaFuncAttributeMaxDynamicSharedMemorySize, OUT_SMEM);
        attr_set = true;
    }

    proj_kernel<<<dim3(Pk / 128, Bk, 3), 256>>>(rgb, depth, rgbd,
                                                Wq, bq, Wk, bk, Wv, bv);
    attn_kernel<<<dim3(Pk / 128, HEADSk, Bk), 256>>>();
    out_kernel<<<dim3(Pk / 64, 2, Bk), 256, OUT_SMEM>>>(rgb, depth, rgbd, Wo, bo, out);
}

// round 17
// speedup vs baseline: 1.0674x; 1.0196x over previous
#include <cuda_runtime.h>
#include <cuda_fp16.h>

#define Bk      4
#define Ck      256
#define Pk      2304      // 48*48
#define INTERk  128
#define HEADSk  8
#define HDk     16

typedef unsigned long long u64;
typedef unsigned int u32;

// ---- helpers --------------------------------------------------------------
__device__ __forceinline__ u32 h2(float lo, float hi) {
    u32 r; asm("cvt.rn.f16x2.f32 %0,%1,%2;" : "=r"(r) : "f"(hi), "f"(lo)); return r;
}
__device__ __forceinline__ u32 ex2h2(u32 x) {
    u32 r; asm("ex2.approx.f16x2 %0,%1;" : "=r"(r) : "r"(x)); return r;
}
__device__ __forceinline__ u32 hadd2(u32 a, u32 b) {
    u32 r; asm("add.rn.f16x2 %0,%1,%2;" : "=r"(r) : "r"(a), "r"(b)); return r;
}
__device__ __forceinline__ float2 h2f(u32 h) {
    float2 f;
    asm("{.reg .f16 l,h; mov.b32 {l,h},%2; cvt.f32.f16 %0,l; cvt.f32.f16 %1,h;}"
        : "=f"(f.x), "=f"(f.y) : "r"(h));
    return f;
}
__device__ __forceinline__ void mma16816(float c[4], const u32 a[4], const u32 b[2]) {
    asm("mma.sync.aligned.m16n8k16.row.col.f32.f16.f16.f32 "
        "{%0,%1,%2,%3},{%4,%5,%6,%7},{%8,%9},{%0,%1,%2,%3};"
        : "+f"(c[0]), "+f"(c[1]), "+f"(c[2]), "+f"(c[3])
        : "r"(a[0]), "r"(a[1]), "r"(a[2]), "r"(a[3]), "r"(b[0]), "r"(b[1]));
}
__device__ __forceinline__ void mma16816hz(u32 d[2], const u32 a[4], const u32 b[2]) {
    asm("mma.sync.aligned.m16n8k16.row.col.f16.f16.f16.f16 "
        "{%0,%1},{%2,%3,%4,%5},{%6,%7},{%8,%9};"
        : "=r"(d[0]), "=r"(d[1])
        : "r"(a[0]), "r"(a[1]), "r"(a[2]), "r"(a[3]), "r"(b[0]), "r"(b[1]),
          "r"(0u), "r"(0u));
}
__device__ __forceinline__ u32 smaddr(const void* p) {
    return (u32)__cvta_generic_to_shared(p);
}
__device__ __forceinline__ void ldmT4(u32 a[4], u32 addr) {
    asm volatile("ldmatrix.sync.aligned.m8n8.x4.trans.shared.b16 {%0,%1,%2,%3},[%4];"
        : "=r"(a[0]), "=r"(a[1]), "=r"(a[2]), "=r"(a[3]) : "r"(addr) : "memory");
}
__device__ __forceinline__ void ldmT2(u32 b[2], u32 addr) {
    asm volatile("ldmatrix.sync.aligned.m8n8.x2.trans.shared.b16 {%0,%1},[%2];"
        : "=r"(b[0]), "=r"(b[1]) : "r"(addr) : "memory");
}
__device__ __forceinline__ void ldm4(u32 a[4], u32 addr) {
    asm volatile("ldmatrix.sync.aligned.m8n8.x4.shared.b16 {%0,%1,%2,%3},[%4];"
        : "=r"(a[0]), "=r"(a[1]), "=r"(a[2]), "=r"(a[3]) : "r"(addr) : "memory");
}
__device__ __forceinline__ void ldA(u32 a[4], const __half* base, int stride,
                                    int mbase, int kbase, int lane) {
    const __half* p = base + (size_t)(mbase + (lane >> 2)) * stride + kbase + (lane & 3) * 2;
    a[0] = *(const u32*)p;
    a[1] = *(const u32*)(p + 8 * stride);
    a[2] = *(const u32*)(p + 8);
    a[3] = *(const u32*)(p + 8 * stride + 8);
}
__device__ __forceinline__ void ldB(u32 b[2], const __half* base, int stride,
                                    int nbase, int kbase, int lane) {
    const __half* p = base + (size_t)(nbase + (lane >> 2)) * stride + kbase + (lane & 3) * 2;
    b[0] = *(const u32*)p;
    b[1] = *(const u32*)(p + 8);
}

// Scratch (device globals), all fp16
__device__ __half gQ[(size_t)Bk * HEADSk * Pk * HDk];   // [b][h][p][d], pre-scaled
__device__ __half gK[(size_t)Bk * HEADSk * Pk * HDk];   // [b][h][p][d]
__device__ __half gVt[(size_t)Bk * HEADSk * HDk * Pk];  // [b][h][d][p]
__device__ __half gO[(size_t)Bk * Pk * INTERk];         // [b][p][ci]

#define WS_STRIDE 40
#define XS3       72    // X row stride for 64-px tiles: 144B rows, conflict-free ldmatrix

// ---------------------------------------------------------------------------
// Kernel 1: QKV projection, fp16 HMMA, 64px x 128co tile (px-split for occ).
// grid = (Pk/64, B, 3), block 256, 3 CTAs/SM.
// ---------------------------------------------------------------------------
__global__ __launch_bounds__(256, 3) void proj_kernel(
    const float* __restrict__ rgb, const float* __restrict__ depth, const float* __restrict__ rgbd,
    const float* __restrict__ Wq, const float* __restrict__ bq,
    const float* __restrict__ Wk, const float* __restrict__ bk,
    const float* __restrict__ Wv, const float* __restrict__ bv)
{
    __shared__ __half Ws[2][128 * WS_STRIDE];
    __shared__ __half Xs[2][32 * XS3];

    const int z = blockIdx.z;
    const float* x    = (z == 0) ? rgb : (z == 1) ? depth : rgbd;
    const float* W    = (z == 0) ? Wq  : (z == 1) ? Wk    : Wv;
    const float* bias = (z == 0) ? bq  : (z == 1) ? bk    : bv;

    const int b    = blockIdx.y;
    const int px0  = blockIdx.x * 64;
    const int t    = threadIdx.x;
    const int lane = t & 31;
    const int w    = t >> 5;

    const int wm  = w >> 2, wn  = w & 3;   // z<2:  px 32-blk (2), co 32-blk (4)
    const int wm2 = w & 3,  wn2 = w >> 2;  // z==2: co 32-blk (4), px 32-blk (2)

    float c[8][4];
    #pragma unroll
    for (int i = 0; i < 8; i++)
        #pragma unroll
        for (int j = 0; j < 4; j++) c[i][j] = 0.f;

    const float* xb = x + (size_t)b * Ck * Pk + px0;

    float4 pw0, pw1, pw2, pw3;
    float4 pxa0, pxa1;

    const int wco = t >> 1, wkh = (t & 1) * 16;
    const int xk  = t >> 3, xp8 = (t & 7) * 8;

    auto ldg_chunk = [&](int kc) {
        const int ci0 = kc * 32;
        const float* wr = W + (size_t)wco * Ck + ci0 + wkh;
        pw0 = *(const float4*)(wr + 0);
        pw1 = *(const float4*)(wr + 4);
        pw2 = *(const float4*)(wr + 8);
        pw3 = *(const float4*)(wr + 12);
        const float* xr = xb + (size_t)(ci0 + xk) * Pk + xp8;
        pxa0 = *(const float4*)(xr);
        pxa1 = *(const float4*)(xr + 4);
    };
    auto sts_chunk = [&](int buf) {
        uint4 p0, p1;
        p0.x = h2(pw0.x, pw0.y); p0.y = h2(pw0.z, pw0.w);
        p0.z = h2(pw1.x, pw1.y); p0.w = h2(pw1.z, pw1.w);
        p1.x = h2(pw2.x, pw2.y); p1.y = h2(pw2.z, pw2.w);
        p1.z = h2(pw3.x, pw3.y); p1.w = h2(pw3.z, pw3.w);
        *(uint4*)&Ws[buf][wco * WS_STRIDE + wkh]     = p0;
        *(uint4*)&Ws[buf][wco * WS_STRIDE + wkh + 8] = p1;
        uint4 xa;
        xa.x = h2(pxa0.x, pxa0.y); xa.y = h2(pxa0.z, pxa0.w);
        xa.z = h2(pxa1.x, pxa1.y); xa.w = h2(pxa1.z, pxa1.w);
        *(uint4*)&Xs[buf][xk * XS3 + xp8] = xa;
    };

    ldg_chunk(0);
    sts_chunk(0);

    #pragma unroll 2
    for (int kc = 0; kc < 8; kc++) {
        __syncthreads();
        if (kc < 7) ldg_chunk(kc + 1);

        const int buf = kc & 1;
        const __half* XsB = &Xs[buf][0];
        const __half* WsB = &Ws[buf][0];

        if (z < 2) {
            #pragma unroll
            for (int k16 = 0; k16 < 2; k16++) {
                const int row = k16 * 16 + ((lane & 16) >> 1) + (lane & 7);
                #pragma unroll
                for (int mt = 0; mt < 2; mt++) {
                    u32 a[4];
                    ldmT4(a, smaddr(XsB + row * XS3 + wm * 32 + mt * 16 + (lane & 8)));
                    #pragma unroll
                    for (int nt = 0; nt < 4; nt++) {
                        u32 bb[2];
                        ldB(bb, WsB, WS_STRIDE, wn * 32 + nt * 8, k16 * 16, lane);
                        mma16816(c[mt * 4 + nt], a, bb);
                    }
                }
            }
        } else {
            #pragma unroll
            for (int k16 = 0; k16 < 2; k16++) {
                const int rowB = k16 * 16 + (lane & 15);
                #pragma unroll
                for (int mt = 0; mt < 2; mt++) {
                    u32 a[4];
                    ldA(a, WsB, WS_STRIDE, wm2 * 32 + mt * 16, k16 * 16, lane);
                    #pragma unroll
                    for (int nt = 0; nt < 4; nt++) {
                        u32 bb[2];
                        ldmT2(bb, smaddr(XsB + rowB * XS3 + wn2 * 32 + nt * 8));
                        mma16816(c[mt * 4 + nt], a, bb);
                    }
                }
            }
        }
        if (kc < 7) sts_chunk((kc + 1) & 1);
    }

    // epilogue
    if (z < 2) {
        const float sc = (z == 0) ? 0.360673760f : 1.0f;   // Q: 0.25*log2(e)
        __half* dst = (z == 0) ? gQ : gK;
        #pragma unroll
        for (int mt = 0; mt < 2; mt++)
            #pragma unroll
            for (int nt = 0; nt < 4; nt++) {
                const float* cc = c[mt * 4 + nt];
                const int px = px0 + wm * 32 + mt * 16 + (lane >> 2);
                const int co = wn * 32 + nt * 8 + (lane & 3) * 2;
                const int head = co >> 4, d = co & 15;
                const size_t base = (size_t)(b * HEADSk + head) * Pk;
                const float b0 = bias[co], b1 = bias[co + 1];
                *(u32*)&dst[(base + px) * HDk + d]     = h2((cc[0] + b0) * sc, (cc[1] + b1) * sc);
                *(u32*)&dst[(base + px + 8) * HDk + d] = h2((cc[2] + b0) * sc, (cc[3] + b1) * sc);
            }
    } else {
        #pragma unroll
        for (int mt = 0; mt < 2; mt++)
            #pragma unroll
            for (int nt = 0; nt < 4; nt++) {
                const float* cc = c[mt * 4 + nt];
                const int px = px0 + wn2 * 32 + nt * 8 + (lane & 3) * 2;
                #pragma unroll
                for (int half = 0; half < 2; half++) {
                    const int co = wm2 * 32 + mt * 16 + (lane >> 2) + half * 8;
                    const int head = co >> 4, d = co & 15;
                    const float bb = bias[co];
                    *(u32*)&gVt[((size_t)(b * HEADSk + head) * HDk + d) * Pk + px] =
                        h2(cc[half * 2] + bb, cc[half * 2 + 1] + bb);
                }
            }
    }
}

// ---------------------------------------------------------------------------
// Kernel 2: attention (unchanged from R13).
// ---------------------------------------------------------------------------
__global__ __launch_bounds__(256, 2) void attn_kernel()
{
    __shared__ __half Ks[2][128][24];
    __shared__ __half Vs[2][16][136];

    const int tid  = threadIdx.x;
    const int lane = tid & 31;
    const int w    = tid >> 5;
    const int b = blockIdx.z, h = blockIdx.y;
    const size_t bh = (size_t)(b * HEADSk + h);
    const int qw = blockIdx.x * 128 + w * 16;

    const __half* Qb = gQ  + bh * Pk * HDk;
    const __half* Kb = gK  + bh * Pk * HDk;
    const __half* Vb = gVt + bh * HDk * Pk;

    u32 aQ[4];
    {
        const __half* qp = Qb + (size_t)(qw + (lane >> 2)) * HDk + (lane & 3) * 2;
        aQ[0] = *(const u32*)(qp);
        aQ[1] = *(const u32*)(qp + 8 * HDk);
        aQ[2] = *(const u32*)(qp + 8);
        aQ[3] = *(const u32*)(qp + 8 * HDk + 8);
    }

    float O0[4] = {0.f, 0.f, 0.f, 0.f};
    float O1[4] = {0.f, 0.f, 0.f, 0.f};
    float l0 = 0.f, l1 = 0.f;

    uint4 pk0, pk1, pv;
    const int vd = tid >> 4, vseg = (tid & 15) * 8;

    auto ldg_tile = [&](int kt) {
        if (tid < 128) {
            const uint4* src = (const uint4*)(Kb + (size_t)(kt + tid) * HDk);
            pk0 = src[0];
            pk1 = src[1];
        }
        pv = *(const uint4*)(Vb + (size_t)vd * Pk + kt + vseg);
    };
    auto sts_tile = [&](int buf) {
        if (tid < 128) {
            *(uint4*)&Ks[buf][tid][0] = pk0;
            *(uint4*)&Ks[buf][tid][8] = pk1;
        }
        *(uint4*)&Vs[buf][vd][vseg] = pv;
    };

    ldg_tile(0);
    sts_tile(0);

    const int krow_lo = ((lane >> 4) * 8) + (lane & 7);
    const int kcol    = ((lane >> 3) & 1) * 8;
    const int vrow    = (lane & 7) + ((lane >> 4) * 8);

    #pragma unroll 2
    for (int it = 0; it < Pk / 128; it++) {
        __syncthreads();
        if (it < Pk / 128 - 1) ldg_tile((it + 1) * 128);
        const int buf = it & 1;

        u32 e[16][2];
        #pragma unroll
        for (int ntp = 0; ntp < 8; ntp++) {
            u32 bK[4];
            ldm4(bK, smaddr(&Ks[buf][ntp * 16 + krow_lo][kcol]));
            u32 d0[2], d1[2];
            mma16816hz(d0, aQ, bK);
            mma16816hz(d1, aQ, bK + 2);
            e[ntp * 2][0]     = ex2h2(d0[0]);
            e[ntp * 2][1]     = ex2h2(d0[1]);
            e[ntp * 2 + 1][0] = ex2h2(d1[0]);
            e[ntp * 2 + 1][1] = ex2h2(d1[1]);
        }

        u32 ta = e[0][0], tb = e[0][1];
        #pragma unroll
        for (int nt = 1; nt < 16; nt++) {
            ta = hadd2(ta, e[nt][0]);
            tb = hadd2(tb, e[nt][1]);
        }
        const float2 fa = h2f(ta), fb = h2f(tb);
        l0 += fa.x + fa.y;
        l1 += fb.x + fb.y;

        #pragma unroll
        for (int kk = 0; kk < 8; kk++) {
            u32 aP[4];
            aP[0] = e[2 * kk][0];
            aP[1] = e[2 * kk][1];
            aP[2] = e[2 * kk + 1][0];
            aP[3] = e[2 * kk + 1][1];
            u32 bV[4];
            ldm4(bV, smaddr(&Vs[buf][vrow][kk * 16 + kcol]));
            mma16816(O0, aP, bV);
            mma16816(O1, aP, bV + 2);
        }
        if (it < Pk / 128 - 1) sts_tile((it + 1) & 1);
    }

    l0 += __shfl_xor_sync(0xffffffffu, l0, 1);
    l0 += __shfl_xor_sync(0xffffffffu, l0, 2);
    l1 += __shfl_xor_sync(0xffffffffu, l1, 1);
    l1 += __shfl_xor_sync(0xffffffffu, l1, 2);
    const float i0 = 1.f / l0;
    const float i1 = 1.f / l1;

    const int q = qw + (lane >> 2);
    __half* Ob = gO + ((size_t)b * Pk) * INTERk + h * HDk;
    #pragma unroll
    for (int nd = 0; nd < 2; nd++) {
        const float* o = nd ? O1 : O0;
        const int d = nd * 8 + (lane & 3) * 2;
        *(u32*)&Ob[(size_t)q * INTERk + d]       = h2(o[0] * i0, o[1] * i0);
        *(u32*)&Ob[(size_t)(q + 8) * INTERk + d] = h2(o[2] * i1, o[3] * i1);
    }
}

// ---------------------------------------------------------------------------
// Kernel 3: output projection, single-stage GEMM + smem-staged COALESCED
// residual epilogue. grid = (P/64, 2, B), block = 256.
// C-stage stride 68 floats (272 B): 16B-aligned rows for float4 reads.
// ---------------------------------------------------------------------------
#define OUT_SMEM ((128 + 64) * 136 * 2)   // 52224 B; Cs [128][68] f32 = 34816 fits

__global__ __launch_bounds__(256) void out_kernel(
    const float* __restrict__ rgb, const float* __restrict__ depth, const float* __restrict__ rgbd,
    const float* __restrict__ Wo, const float* __restrict__ bo,
    float* __restrict__ out)
{
    extern __shared__ __half dsm[];
    __half* Wos = dsm;              // [128][136]
    __half* Os  = dsm + 128 * 136;  // [64][136]

    const int b    = blockIdx.z;
    const int cob  = blockIdx.y;
    const int px0  = blockIdx.x * 64;
    const int t    = threadIdx.x;
    const int lane = t & 31;
    const int w    = t >> 5;
    const int wm   = w >> 1;
    const int wn   = w & 1;

    {
        const int co = t >> 1, ci0 = (t & 1) * 64;
        const float* wr = Wo + (size_t)(cob * 128 + co) * INTERk + ci0;
        #pragma unroll
        for (int i = 0; i < 4; i++) {
            const float4 f0 = *(const float4*)(wr + i * 16);
            const float4 f1 = *(const float4*)(wr + i * 16 + 4);
            const float4 f2 = *(const float4*)(wr + i * 16 + 8);
            const float4 f3 = *(const float4*)(wr + i * 16 + 12);
            uint4 p, q;
            p.x = h2(f0.x, f0.y); p.y = h2(f0.z, f0.w);
            p.z = h2(f1.x, f1.y); p.w = h2(f1.z, f1.w);
            q.x = h2(f2.x, f2.y); q.y = h2(f2.z, f2.w);
            q.z = h2(f3.x, f3.y); q.w = h2(f3.z, f3.w);
            *(uint4*)&Wos[co * 136 + ci0 + i * 16]     = p;
            *(uint4*)&Wos[co * 136 + ci0 + i * 16 + 8] = q;
        }
    }
    {
        const int px = t >> 2, ci0 = (t & 3) * 32;
        const __half* src = gO + ((size_t)b * Pk + px0 + px) * INTERk + ci0;
        *(uint4*)&Os[px * 136 + ci0]      = *(const uint4*)(src);
        *(uint4*)&Os[px * 136 + ci0 + 8]  = *(const uint4*)(src + 8);
        *(uint4*)&Os[px * 136 + ci0 + 16] = *(const uint4*)(src + 16);
        *(uint4*)&Os[px * 136 + ci0 + 24] = *(const uint4*)(src + 24);
    }
    // L2 prefetch of residual inputs (consumed in the write phase)
    {
        const int co = t >> 1, half = t & 1;
        const size_t idx = ((size_t)b * Ck + cob * 128 + co) * Pk + px0 + half * 32;
        asm volatile("prefetch.global.L2 [%0];" :: "l"(rgb + idx));
        asm volatile("prefetch.global.L2 [%0];" :: "l"(depth + idx));
        asm volatile("prefetch.global.L2 [%0];" :: "l"(rgbd + idx));
    }
    __syncthreads();

    float c[8][4];
    #pragma unroll
    for (int i = 0; i < 8; i++)
        #pragma unroll
        for (int j = 0; j < 4; j++) c[i][j] = 0.f;

    #pragma unroll
    for (int k16 = 0; k16 < 8; k16++) {
        u32 a0[4], a1[4];
        ldA(a0, Wos, 136, wm * 32,      k16 * 16, lane);
        ldA(a1, Wos, 136, wm * 32 + 16, k16 * 16, lane);
        #pragma unroll
        for (int nt = 0; nt < 4; nt++) {
            u32 bb[2];
            ldB(bb, Os, 136, wn * 32 + nt * 8, k16 * 16, lane);
            mma16816(c[nt],     a0, bb);
            mma16816(c[4 + nt], a1, bb);
        }
    }

    // stage C (+bias) to smem [128 co][68 px-stride] fp32, then coalesced writes
    __syncthreads();                      // Wos/Os dead; reuse as Cs
    float* Cs = (float*)dsm;              // [128][68]
    #pragma unroll
    for (int mt = 0; mt < 2; mt++)
        #pragma unroll
        for (int nt = 0; nt < 4; nt++) {
            const float* cc = c[mt * 4 + nt];
            const int pxl = wn * 32 + nt * 8 + (lane & 3) * 2;
            #pragma unroll
            for (int half = 0; half < 2; half++) {
                const int col = wm * 32 + mt * 16 + (lane >> 2) + half * 8;
                const float bb = bo[cob * 128 + col];
                *(float2*)&Cs[col * 68 + pxl] =
                    make_float2(cc[half * 2] + bb, cc[half * 2 + 1] + bb);
            }
        }
    __syncthreads();

    const size_t N1 = (size_t)Bk * Ck * Pk;
    #pragma unroll
    for (int itr = 0; itr < 8; itr++) {
        const int pos = (itr * 256 + t) * 4;     // 8192 floats total
        const int row = pos >> 6;
        const int pxl = pos & 63;
        const float4 cv = *(const float4*)&Cs[row * 68 + pxl];
        const size_t idx = ((size_t)b * Ck + cob * 128 + row) * Pk + px0 + pxl;
        const float4 a0 = *(const float4*)(rgb   + idx);
        const float4 a1 = *(const float4*)(depth + idx);
        const float4 a2 = *(const float4*)(rgbd  + idx);
        *(float4*)(out + idx)          = make_float4(a0.x + cv.x, a0.y + cv.y, a0.z + cv.z, a0.w + cv.w);
        *(float4*)(out + N1 + idx)     = make_float4(a1.x + cv.x, a1.y + cv.y, a1.z + cv.z, a1.w + cv.w);
        *(float4*)(out + 2 * N1 + idx) = make_float4(a2.x + cv.x, a2.y + cv.y, a2.z + cv.z, a2.w + cv.w);
    }
}

// ---------------------------------------------------------------------------
extern "C" void kernel_launch(void* const* d_in, const int* in_sizes, int n_in,
                              void* d_out, int out_size)
{
    const float* rgb   = (const float*)d_in[0];
    const float* depth = (const float*)d_in[1];
    const float* rgbd  = (const float*)d_in[2];
    const float* Wq = (const float*)d_in[3];
    const float* bq = (const float*)d_in[4];
    const float* Wk = (const float*)d_in[5];
    const float* bk = (const float*)d_in[6];
    const float* Wv = (const float*)d_in[7];
    const float* bv = (const float*)d_in[8];
    const float* Wo = (const float*)d_in[9];
    const float* bo = (const float*)d_in[10];
    float* out = (float*)d_out;

    static bool attr_set = false;
    if (!attr_set) {
        cudaFuncSetAttribute(out_kernel, cudaFuncAttributeMaxDynamicSharedMemorySize, OUT_SMEM);
        attr_set = true;
    }

    proj_kernel<<<dim3(Pk / 64, Bk, 3), 256>>>(rgb, depth, rgbd,
                                               Wq, bq, Wk, bk, Wv, bv);
    attn_kernel<<<dim3(Pk / 128, HEADSk, Bk), 256>>>();
    out_kernel<<<dim3(Pk / 64, 2, Bk), 256, OUT_SMEM>>>(rgb, depth, rgbd, Wo, bo, out);
}